// round 11
// baseline (speedup 1.0000x reference)
#include <cuda_runtime.h>
#include <cuda_fp16.h>
#include <math.h>
#include <stdint.h>

#define NIMG  256
#define PLANE 65536
#define TOT   16777216

// Scratch (__device__ globals per allocation rules)
__device__ uint32_t g_AB[TOT];         // packed half2 (a, b) per element
__device__ uint32_t g_O1p[TOT/2];      // layer1 output, channel-pair half2 packed
__device__ float    g_hdump[4*PLANE];
__device__ uint32_t g_U1[32768];       // Winograd-transformed weights, fragment order
__device__ uint32_t g_U2[65536];

__device__ __forceinline__ float sigm(float x) { return 1.f/(1.f+__expf(-x)); }
__device__ __forceinline__ uint32_t pkh2(float a, float b) {
    __half2 h = __floats2half2_rn(a, b);
    return *(uint32_t*)&h;
}

// Pack Winograd-transformed weights U = G w G^T (4x4 per oc,ic) into mma-fragment
// order: slab = (p*4 + ocgrp)*2 + f ; per slab KC chunks of 128 u32 (lane*4 + q).
template<int IC>
__global__ void pack_u(const float* __restrict__ w, uint32_t* __restrict__ dst) {
    constexpr int KC = IC / 16;
    int idx = blockIdx.x * 256 + threadIdx.x;
    if (idx >= 128 * KC * 128) return;
    int slab = idx / (KC * 128);
    int rem  = idx - slab * (KC * 128);
    int c = rem >> 7, rem2 = rem & 127;
    int lane = rem2 >> 2, q = rem2 & 3;
    int f  = slab & 1;
    int og = (slab >> 1) & 3;
    int p  = slab >> 3;
    int xi = p >> 2, eta = p & 3;
    int oc = f * 64 + og * 16 + (lane >> 2) + (q & 1) * 8;
    int k  = c * 16 + 2 * (lane & 3) + (q >> 1) * 8;
    const float G[4][3] = {{1,0,0},{0.5f,0.5f,0.5f},{0.5f,-0.5f,0.5f},{0,0,1}};
    float u[2];
    #pragma unroll
    for (int t = 0; t < 2; t++) {
        const float* wp = w + (oc * IC + k + t) * 9;
        float a = 0.f;
        for (int i = 0; i < 3; i++)
            for (int j = 0; j < 3; j++)
                a += G[xi][i] * G[eta][j] * wp[i * 3 + j];
        u[t] = a;
    }
    dst[idx] = pkh2(u[0], u[1]);
}

// Winograd F(2x2,3x3) conv + fused minGRU epilogue. R8 body, occupancy-2 shape:
// Grid 2048 = 256 images x 8 bands (4 rows = 2 tile-rows). 256 threads = 8 warps,
// 2 CTAs/SM (regs 51K, smem 214KB) -> one CTA's transform/fold/epilogue overlaps
// the other's mma stream. Warp (og, tg): 32oc x tile-row tg. No in-loop syncs.
template<int IC, bool PIN>
__global__ void __launch_bounds__(256, 2)
conv_wino(const void* __restrict__ xin_, const uint32_t* __restrict__ Upk,
          const float* __restrict__ bias, uint32_t* __restrict__ ABout)
{
    extern __shared__ uint32_t sm[];
    constexpr int KC  = IC / 16;
    constexpr int ICP = IC / 2;
    constexpr int VP  = ICP * 40;          // u32 per transform point (32 tiles, pad 40)
    uint32_t* tile2 = sm;                  // [ICP][6 rows][36 cols] half2
    uint32_t* V     = sm + ICP * 216;      // [16 points][ICP kpairs][40 (32 tiles)]

    const int tid = threadIdx.x;
    const int wv = tid >> 5, lane = tid & 31;
    const int g4 = lane >> 2, tig = lane & 3;
    const int og = wv & 3, tg = wv >> 2;   // tg in {0,1}
    const int blk = blockIdx.x, band = blk & 7, n = blk >> 3, r0 = band * 4;

    // Stage padded input: rows r0-1..r0+4 (6), cols -1..33 (36), channel-pair half2
    for (int idx = tid; idx < ICP * 216; idx += 256) {
        int icp = idx / 216, rem = idx - icp * 216, r = rem / 36, c = rem - r * 36;
        int gr = r0 + r - 1, gc = c - 1;
        uint32_t v = 0;
        if ((unsigned)gr < 32u && (unsigned)gc < 32u) {
            if (PIN) {
                v = ((const uint32_t*)xin_)[n * 32768 + icp * 1024 + (gr << 5) + gc];
            } else {
                const float* x = (const float*)xin_;
                int base = ((n * IC + 2 * icp) << 10) + (gr << 5) + gc;
                v = pkh2(x[base], x[base + 1024]);
            }
        }
        tile2[idx] = v;
    }
    __syncthreads();

    // Input transform (R8 float2 arithmetic): V = B^T d B per (icpair, tile)
    for (int u = tid; u < ICP * 32; u += 256) {
        int icp = u >> 5, t5 = u & 31, tr = t5 >> 4, tc = t5 & 15;
        const uint32_t* dp = tile2 + icp * 216 + (2 * tr) * 36 + 2 * tc;
        float2 d[4][4];
        #pragma unroll
        for (int i = 0; i < 4; i++)
            #pragma unroll
            for (int j = 0; j < 4; j++) {
                uint32_t raw = dp[i * 36 + j];
                d[i][j] = __half22float2(*(__half2*)&raw);
            }
        float2 t[4][4];
        #pragma unroll
        for (int j = 0; j < 4; j++) {
            t[0][j] = make_float2(d[0][j].x - d[2][j].x, d[0][j].y - d[2][j].y);
            t[1][j] = make_float2(d[1][j].x + d[2][j].x, d[1][j].y + d[2][j].y);
            t[2][j] = make_float2(d[2][j].x - d[1][j].x, d[2][j].y - d[1][j].y);
            t[3][j] = make_float2(d[1][j].x - d[3][j].x, d[1][j].y - d[3][j].y);
        }
        uint32_t* vp = V + icp * 40 + tr * 16 + tc;
        #pragma unroll
        for (int xi = 0; xi < 4; xi++) {
            float2 v0 = make_float2(t[xi][0].x - t[xi][2].x, t[xi][0].y - t[xi][2].y);
            float2 v1 = make_float2(t[xi][1].x + t[xi][2].x, t[xi][1].y + t[xi][2].y);
            float2 v2 = make_float2(t[xi][2].x - t[xi][1].x, t[xi][2].y - t[xi][1].y);
            float2 v3 = make_float2(t[xi][1].x - t[xi][3].x, t[xi][1].y - t[xi][3].y);
            vp[(xi * 4 + 0) * VP] = pkh2(v0.x, v0.y);
            vp[(xi * 4 + 1) * VP] = pkh2(v1.x, v1.y);
            vp[(xi * 4 + 2) * VP] = pkh2(v2.x, v2.y);
            vp[(xi * 4 + 3) * VP] = pkh2(v3.x, v3.y);
        }
    }
    __syncthreads();

    float Y[2][2][4][4];   // [f gate/hid][nf][acc j][di*2+dj]
    #pragma unroll
    for (int f = 0; f < 2; f++)
        #pragma unroll
        for (int nf = 0; nf < 2; nf++)
            #pragma unroll
            for (int j = 0; j < 4; j++)
                #pragma unroll
                for (int e = 0; e < 4; e++) Y[f][nf][j][e] = 0.f;

    for (int p = 0; p < 16; p++) {         // runtime loop, small uniform body (R8)
        float M[2][2][4];
        #pragma unroll
        for (int f = 0; f < 2; f++)
            #pragma unroll
            for (int nf = 0; nf < 2; nf++)
                #pragma unroll
                for (int j = 0; j < 4; j++) M[f][nf][j] = 0.f;

        const uint32_t* Ub = Upk + ((p * 4 + og) * 2) * KC * 128;
        const uint32_t* Vb = V + p * VP + tig * 40 + tg * 16 + g4;
        #pragma unroll
        for (int c = 0; c < KC; c++) {
            uint4 a0 = *(const uint4*)(Ub + c * 128 + lane * 4);
            uint4 a1 = *(const uint4*)(Ub + KC * 128 + c * 128 + lane * 4);
            uint32_t b00 = Vb[(c * 8) * 40];
            uint32_t b01 = Vb[(c * 8 + 4) * 40];
            uint32_t b10 = Vb[(c * 8) * 40 + 8];
            uint32_t b11 = Vb[(c * 8 + 4) * 40 + 8];
            #pragma unroll
            for (int f = 0; f < 2; f++) {
                uint4 aa = f ? a1 : a0;
                asm volatile(
                    "mma.sync.aligned.m16n8k16.row.col.f32.f16.f16.f32 "
                    "{%0,%1,%2,%3}, {%4,%5,%6,%7}, {%8,%9}, {%0,%1,%2,%3};"
                    : "+f"(M[f][0][0]), "+f"(M[f][0][1]), "+f"(M[f][0][2]), "+f"(M[f][0][3])
                    : "r"(aa.x), "r"(aa.y), "r"(aa.z), "r"(aa.w), "r"(b00), "r"(b01));
                asm volatile(
                    "mma.sync.aligned.m16n8k16.row.col.f32.f16.f16.f32 "
                    "{%0,%1,%2,%3}, {%4,%5,%6,%7}, {%8,%9}, {%0,%1,%2,%3};"
                    : "+f"(M[f][1][0]), "+f"(M[f][1][1]), "+f"(M[f][1][2]), "+f"(M[f][1][3])
                    : "r"(aa.x), "r"(aa.y), "r"(aa.z), "r"(aa.w), "r"(b10), "r"(b11));
            }
        }
        // Runtime A^T fold (R8): At0 = [1,1,1,0], At1 = [0,1,-1,-1]
        int xi = p >> 2, eta = p & 3;
        float cx0 = (xi == 3) ? 0.f : 1.f;
        float cx1 = (xi == 0) ? 0.f : ((xi == 1) ? 1.f : -1.f);
        float cy0 = (eta == 3) ? 0.f : 1.f;
        float cy1 = (eta == 0) ? 0.f : ((eta == 1) ? 1.f : -1.f);
        float c00 = cx0 * cy0, c01 = cx0 * cy1, c10 = cx1 * cy0, c11 = cx1 * cy1;
        #pragma unroll
        for (int f = 0; f < 2; f++)
            #pragma unroll
            for (int nf = 0; nf < 2; nf++)
                #pragma unroll
                for (int j = 0; j < 4; j++) {
                    float m = M[f][nf][j];
                    Y[f][nf][j][0] = fmaf(c00, m, Y[f][nf][j][0]);
                    Y[f][nf][j][1] = fmaf(c01, m, Y[f][nf][j][1]);
                    Y[f][nf][j][2] = fmaf(c10, m, Y[f][nf][j][2]);
                    Y[f][nf][j][3] = fmaf(c11, m, Y[f][nf][j][3]);
                }
    }

    // Fused minGRU epilogue -> packed half2 (a, b), uint2 per 2x1 px pair
    const float bg0 = __ldg(bias + og * 16 + g4),      bg1 = __ldg(bias + og * 16 + g4 + 8);
    const float bh0 = __ldg(bias + 64 + og * 16 + g4), bh1 = __ldg(bias + 64 + og * 16 + g4 + 8);
    #pragma unroll
    for (int nf = 0; nf < 2; nf++)
        #pragma unroll
        for (int j = 0; j < 4; j++) {
            int oc = og * 16 + g4 + ((j >> 1) * 8);
            int tc = nf * 8 + 2 * tig + (j & 1);
            float bg = (j >> 1) ? bg1 : bg0, bh = (j >> 1) ? bh1 : bh0;
            #pragma unroll
            for (int di = 0; di < 2; di++) {
                int row = r0 + 2 * tg + di;
                float g0 = Y[0][nf][j][di * 2 + 0] + bg;
                float g1 = Y[0][nf][j][di * 2 + 1] + bg;
                float h0 = Y[1][nf][j][di * 2 + 0] + bh;
                float h1 = Y[1][nf][j][di * 2 + 1] + bh;
                float z0 = sigm(g0), z1 = sigm(g1);
                float q0 = (h0 >= 0.f) ? h0 + 0.5f : sigm(h0);
                float q1 = (h1 >= 0.f) ? h1 + 0.5f : sigm(h1);
                uint2 pk;
                pk.x = pkh2(1.f - z0, z0 * q0);
                pk.y = pkh2(1.f - z1, z1 * q1);
                *(uint2*)(ABout + ((n * 64 + oc) << 10) + (row << 5) + 2 * tc) = pk;
            }
        }
}

// Scan layer 1: one thread per channel PAIR; reads packed (a,b) half2;
// writes packed half2 O1 + fp32 h1.
__global__ void __launch_bounds__(256)
scan1_k(const uint32_t* __restrict__ AB,
        uint32_t* __restrict__ o1p, float* __restrict__ h1)
{
    int idx = blockIdx.x * 256 + threadIdx.x;       // 131072
    int b = idx >> 15, rem = idx & 32767;
    int icp = rem >> 10, px = rem & 1023;
    size_t base = (size_t)b * 64 * 65536 + icp * 2048 + px;
    float h0 = 0.5f, h1v = 0.5f;
    #pragma unroll 8
    for (int t = 0; t < 64; t++) {
        size_t off = base + (size_t)t * 65536;
        uint32_t p0 = AB[off], p1 = AB[off + 1024];
        float2 c0 = __half22float2(*(__half2*)&p0);
        float2 c1 = __half22float2(*(__half2*)&p1);
        h0  = fmaf(c0.x, h0,  c0.y);
        h1v = fmaf(c1.x, h1v, c1.y);
        o1p[(size_t)(b * 64 + t) * 32768 + rem] = pkh2(h0, h1v);
    }
    h1[b * 65536 + icp * 2048 + px]        = h0;
    h1[b * 65536 + icp * 2048 + 1024 + px] = h1v;
}

// Scan layer 2: reads packed (a,b); fp32 out (final), float2 stores.
__global__ void __launch_bounds__(256)
scan2_k(const uint32_t* __restrict__ AB,
        float* __restrict__ out, float* __restrict__ h2)
{
    int idx = blockIdx.x * 256 + threadIdx.x;       // 131072 px-pair lanes
    int b = idx >> 15, j = idx & 32767;
    size_t base = (size_t)b * 64 * 32768 + j;
    const uint2* AB2 = (const uint2*)AB;
    float2* o2 = (float2*)out;
    float h0 = 0.5f, h1v = 0.5f;
    #pragma unroll 8
    for (int t = 0; t < 64; t++) {
        size_t off = base + (size_t)t * 32768;
        uint2 p = AB2[off];
        float2 c0 = __half22float2(*(__half2*)&p.x);
        float2 c1 = __half22float2(*(__half2*)&p.y);
        h0  = fmaf(c0.x, h0,  c0.y);
        h1v = fmaf(c1.x, h1v, c1.y);
        o2[off] = make_float2(h0, h1v);
    }
    ((float2*)h2)[b * 32768 + j] = make_float2(h0, h1v);
}

extern "C" void kernel_launch(void* const* d_in, const int* in_sizes, int n_in,
                              void* d_out, int out_size) {
    const float* x  = (const float*)d_in[0];
    const float* w1 = (const float*)d_in[1];
    const float* b1 = (const float*)d_in[2];
    const float* w2 = (const float*)d_in[3];
    const float* b2 = (const float*)d_in[4];
    float* out = (float*)d_out;

    float *pH;
    uint32_t *pAB, *pO1p, *pU1, *pU2;
    cudaGetSymbolAddress((void**)&pAB,  g_AB);
    cudaGetSymbolAddress((void**)&pO1p, g_O1p);
    cudaGetSymbolAddress((void**)&pH,   g_hdump);
    cudaGetSymbolAddress((void**)&pU1,  g_U1);
    cudaGetSymbolAddress((void**)&pU2,  g_U2);

    const int SMEM1 = (16 * 216 + 16 * 16 * 40) * 4;   //  54784
    const int SMEM2 = (32 * 216 + 16 * 32 * 40) * 4;   // 109568
    cudaFuncSetAttribute(conv_wino<32,false>, cudaFuncAttributeMaxDynamicSharedMemorySize, SMEM1);
    cudaFuncSetAttribute(conv_wino<64,true>,  cudaFuncAttributeMaxDynamicSharedMemorySize, SMEM2);

    bool full = (out_size >= TOT + 8 * PLANE);
    float* h1 = full ? (out + TOT)             : pH;
    float* h2 = full ? (out + TOT + 4 * PLANE) : pH;

    pack_u<32><<<128, 256>>>(w1, pU1);
    pack_u<64><<<256, 256>>>(w2, pU2);
    conv_wino<32,false><<<2048, 256, SMEM1>>>(x, pU1, b1, pAB);
    scan1_k<<<512, 256>>>(pAB, pO1p, h1);
    conv_wino<64,true><<<2048, 256, SMEM2>>>(pO1p, pU2, b2, pAB);
    scan2_k<<<512, 256>>>(pAB, out, h2);
}

// round 12
// speedup vs baseline: 1.4714x; 1.4714x over previous
#include <cuda_runtime.h>
#include <cuda_fp16.h>
#include <math.h>
#include <stdint.h>

#define NIMG  256
#define PLANE 65536
#define TOT   16777216

// Scratch (__device__ globals per allocation rules)
__device__ uint32_t g_AB[TOT];         // packed half2 (a, b) per element
__device__ uint32_t g_O1p[TOT/2];      // layer1 output, channel-pair half2 packed
__device__ float    g_hdump[4*PLANE];
__device__ uint32_t g_U1[32768];       // Winograd-transformed weights, fragment order
__device__ uint32_t g_U2[65536];

__device__ __forceinline__ float sigm(float x) { return 1.f/(1.f+__expf(-x)); }
__device__ __forceinline__ uint32_t pkh2(float a, float b) {
    __half2 h = __floats2half2_rn(a, b);
    return *(uint32_t*)&h;
}

// Pack Winograd-transformed weights U = G w G^T (4x4 per oc,ic) into mma-fragment
// order: slab = (p*4 + ocgrp)*2 + f ; per slab KC chunks of 128 u32 (lane*4 + q).
template<int IC>
__global__ void pack_u(const float* __restrict__ w, uint32_t* __restrict__ dst) {
    constexpr int KC = IC / 16;
    int idx = blockIdx.x * 256 + threadIdx.x;
    if (idx >= 128 * KC * 128) return;
    int slab = idx / (KC * 128);
    int rem  = idx - slab * (KC * 128);
    int c = rem >> 7, rem2 = rem & 127;
    int lane = rem2 >> 2, q = rem2 & 3;
    int f  = slab & 1;
    int og = (slab >> 1) & 3;
    int p  = slab >> 3;
    int xi = p >> 2, eta = p & 3;
    int oc = f * 64 + og * 16 + (lane >> 2) + (q & 1) * 8;
    int k  = c * 16 + 2 * (lane & 3) + (q >> 1) * 8;
    const float G[4][3] = {{1,0,0},{0.5f,0.5f,0.5f},{0.5f,-0.5f,0.5f},{0,0,1}};
    float u[2];
    #pragma unroll
    for (int t = 0; t < 2; t++) {
        const float* wp = w + (oc * IC + k + t) * 9;
        float a = 0.f;
        for (int i = 0; i < 3; i++)
            for (int j = 0; j < 3; j++)
                a += G[xi][i] * G[eta][j] * wp[i * 3 + j];
        u[t] = a;
    }
    dst[idx] = pkh2(u[0], u[1]);
}

// Winograd F(2x2,3x3) conv + fused minGRU epilogue. (R8 configuration, verbatim.)
// Grid 1024 = 256 images x 4 bands (8 rows = 4 tile-rows). 512 threads = 16 warps.
// Warp (og, tg): 32 oc (16 gate og*16.. + paired hidden +64) x tile-row tg (16 tiles).
// Loop 16 transform points: GEMM K=IC from U (gmem, frag-packed) x V (smem),
// fold M into Y via A^T coeffs {0,+-1}. V pitch 72: LDS bank 8*(l%4)+l/4, conflict-free.
template<int IC, bool PIN>
__global__ void __launch_bounds__(512, 1)
conv_wino(const void* __restrict__ xin_, const uint32_t* __restrict__ Upk,
          const float* __restrict__ bias, uint32_t* __restrict__ ABout)
{
    extern __shared__ uint32_t sm[];
    constexpr int KC  = IC / 16;
    constexpr int ICP = IC / 2;
    constexpr int VP  = ICP * 72;          // u32 per transform point
    uint32_t* tile2 = sm;                  // [ICP][10 rows][36 cols] half2
    uint32_t* V     = sm + ICP * 360;      // [16 points][ICP kpairs][72 (64 tiles)]

    const int tid = threadIdx.x;
    const int wv = tid >> 5, lane = tid & 31;
    const int g4 = lane >> 2, tig = lane & 3;
    const int og = wv & 3, tg = wv >> 2;
    const int blk = blockIdx.x, band = blk & 3, n = blk >> 2, r0 = band * 8;

    // Stage padded input: rows r0-1..r0+8 (10), cols -1..33 (36), channel-pair half2
    for (int idx = tid; idx < ICP * 360; idx += 512) {
        int icp = idx / 360, rem = idx - icp * 360, r = rem / 36, c = rem - r * 36;
        int gr = r0 + r - 1, gc = c - 1;
        uint32_t v = 0;
        if ((unsigned)gr < 32u && (unsigned)gc < 32u) {
            if (PIN) {
                v = ((const uint32_t*)xin_)[n * 32768 + icp * 1024 + (gr << 5) + gc];
            } else {
                const float* x = (const float*)xin_;
                int base = ((n * IC + 2 * icp) << 10) + (gr << 5) + gc;
                v = pkh2(x[base], x[base + 1024]);
            }
        }
        tile2[idx] = v;
    }
    __syncthreads();

    // Input transform: per (icpair, tile): V = B^T d B (on half2 = 2 channels at once)
    for (int u = tid; u < ICP * 64; u += 512) {
        int icp = u >> 6, rem = u & 63, tr = rem >> 4, tc = rem & 15;
        const uint32_t* dp = tile2 + icp * 360 + (2 * tr) * 36 + 2 * tc;
        float2 d[4][4];
        #pragma unroll
        for (int i = 0; i < 4; i++)
            #pragma unroll
            for (int j = 0; j < 4; j++) {
                uint32_t raw = dp[i * 36 + j];
                d[i][j] = __half22float2(*(__half2*)&raw);
            }
        float2 t[4][4];
        #pragma unroll
        for (int j = 0; j < 4; j++) {
            t[0][j] = make_float2(d[0][j].x - d[2][j].x, d[0][j].y - d[2][j].y);
            t[1][j] = make_float2(d[1][j].x + d[2][j].x, d[1][j].y + d[2][j].y);
            t[2][j] = make_float2(d[2][j].x - d[1][j].x, d[2][j].y - d[1][j].y);
            t[3][j] = make_float2(d[1][j].x - d[3][j].x, d[1][j].y - d[3][j].y);
        }
        uint32_t* vp = V + icp * 72 + tr * 16 + tc;
        #pragma unroll
        for (int xi = 0; xi < 4; xi++) {
            float2 v0 = make_float2(t[xi][0].x - t[xi][2].x, t[xi][0].y - t[xi][2].y);
            float2 v1 = make_float2(t[xi][1].x + t[xi][2].x, t[xi][1].y + t[xi][2].y);
            float2 v2 = make_float2(t[xi][2].x - t[xi][1].x, t[xi][2].y - t[xi][1].y);
            float2 v3 = make_float2(t[xi][1].x - t[xi][3].x, t[xi][1].y - t[xi][3].y);
            vp[(xi * 4 + 0) * VP] = pkh2(v0.x, v0.y);
            vp[(xi * 4 + 1) * VP] = pkh2(v1.x, v1.y);
            vp[(xi * 4 + 2) * VP] = pkh2(v2.x, v2.y);
            vp[(xi * 4 + 3) * VP] = pkh2(v3.x, v3.y);
        }
    }
    __syncthreads();

    float Y[2][2][4][4];   // [f gate/hid][nf][acc j][di*2+dj]
    #pragma unroll
    for (int f = 0; f < 2; f++)
        #pragma unroll
        for (int nf = 0; nf < 2; nf++)
            #pragma unroll
            for (int j = 0; j < 4; j++)
                #pragma unroll
                for (int e = 0; e < 4; e++) Y[f][nf][j][e] = 0.f;

    for (int p = 0; p < 16; p++) {
        float M[2][2][4];
        #pragma unroll
        for (int f = 0; f < 2; f++)
            #pragma unroll
            for (int nf = 0; nf < 2; nf++)
                #pragma unroll
                for (int j = 0; j < 4; j++) M[f][nf][j] = 0.f;

        const uint32_t* Ub = Upk + (size_t)((p * 4 + og) * 2) * KC * 128;
        const uint32_t* Vb = V + p * VP + tig * 72 + tg * 16 + g4;
        #pragma unroll
        for (int c = 0; c < KC; c++) {
            uint4 a0 = *(const uint4*)(Ub + c * 128 + lane * 4);
            uint4 a1 = *(const uint4*)(Ub + KC * 128 + c * 128 + lane * 4);
            uint32_t b00 = Vb[(c * 8) * 72];
            uint32_t b01 = Vb[(c * 8 + 4) * 72];
            uint32_t b10 = Vb[(c * 8) * 72 + 8];
            uint32_t b11 = Vb[(c * 8 + 4) * 72 + 8];
            #pragma unroll
            for (int f = 0; f < 2; f++) {
                uint4 aa = f ? a1 : a0;
                asm volatile(
                    "mma.sync.aligned.m16n8k16.row.col.f32.f16.f16.f32 "
                    "{%0,%1,%2,%3}, {%4,%5,%6,%7}, {%8,%9}, {%0,%1,%2,%3};"
                    : "+f"(M[f][0][0]), "+f"(M[f][0][1]), "+f"(M[f][0][2]), "+f"(M[f][0][3])
                    : "r"(aa.x), "r"(aa.y), "r"(aa.z), "r"(aa.w), "r"(b00), "r"(b01));
                asm volatile(
                    "mma.sync.aligned.m16n8k16.row.col.f32.f16.f16.f32 "
                    "{%0,%1,%2,%3}, {%4,%5,%6,%7}, {%8,%9}, {%0,%1,%2,%3};"
                    : "+f"(M[f][1][0]), "+f"(M[f][1][1]), "+f"(M[f][1][2]), "+f"(M[f][1][3])
                    : "r"(aa.x), "r"(aa.y), "r"(aa.z), "r"(aa.w), "r"(b10), "r"(b11));
            }
        }
        // Fold M into Y with A^T coeffs: At0 = [1,1,1,0], At1 = [0,1,-1,-1]
        int xi = p >> 2, eta = p & 3;
        float cx0 = (xi == 3) ? 0.f : 1.f;
        float cx1 = (xi == 0) ? 0.f : ((xi == 1) ? 1.f : -1.f);
        float cy0 = (eta == 3) ? 0.f : 1.f;
        float cy1 = (eta == 0) ? 0.f : ((eta == 1) ? 1.f : -1.f);
        float c00 = cx0 * cy0, c01 = cx0 * cy1, c10 = cx1 * cy0, c11 = cx1 * cy1;
        #pragma unroll
        for (int f = 0; f < 2; f++)
            #pragma unroll
            for (int nf = 0; nf < 2; nf++)
                #pragma unroll
                for (int j = 0; j < 4; j++) {
                    float m = M[f][nf][j];
                    Y[f][nf][j][0] = fmaf(c00, m, Y[f][nf][j][0]);
                    Y[f][nf][j][1] = fmaf(c01, m, Y[f][nf][j][1]);
                    Y[f][nf][j][2] = fmaf(c10, m, Y[f][nf][j][2]);
                    Y[f][nf][j][3] = fmaf(c11, m, Y[f][nf][j][3]);
                }
    }

    // Fused minGRU epilogue -> packed half2 (a, b), uint2 per 2x1 px pair
    const float bg0 = __ldg(bias + og * 16 + g4),      bg1 = __ldg(bias + og * 16 + g4 + 8);
    const float bh0 = __ldg(bias + 64 + og * 16 + g4), bh1 = __ldg(bias + 64 + og * 16 + g4 + 8);
    #pragma unroll
    for (int nf = 0; nf < 2; nf++)
        #pragma unroll
        for (int j = 0; j < 4; j++) {
            int oc = og * 16 + g4 + ((j >> 1) * 8);
            int tc = nf * 8 + 2 * tig + (j & 1);
            float bg = (j >> 1) ? bg1 : bg0, bh = (j >> 1) ? bh1 : bh0;
            #pragma unroll
            for (int di = 0; di < 2; di++) {
                int row = r0 + 2 * tg + di;
                float g0 = Y[0][nf][j][di * 2 + 0] + bg;
                float g1 = Y[0][nf][j][di * 2 + 1] + bg;
                float h0 = Y[1][nf][j][di * 2 + 0] + bh;
                float h1 = Y[1][nf][j][di * 2 + 1] + bh;
                float z0 = sigm(g0), z1 = sigm(g1);
                float q0 = (h0 >= 0.f) ? h0 + 0.5f : sigm(h0);
                float q1 = (h1 >= 0.f) ? h1 + 0.5f : sigm(h1);
                uint2 pk;
                pk.x = pkh2(1.f - z0, z0 * q0);
                pk.y = pkh2(1.f - z1, z1 * q1);
                *(uint2*)(ABout + ((n * 64 + oc) << 10) + (row << 5) + 2 * tc) = pk;
            }
        }
}

// Scan layer 1: one thread per channel PAIR; reads packed (a,b) half2;
// writes packed half2 O1 + fp32 h1.  (unroll 8: verified -1.2us)
__global__ void __launch_bounds__(256)
scan1_k(const uint32_t* __restrict__ AB,
        uint32_t* __restrict__ o1p, float* __restrict__ h1)
{
    int idx = blockIdx.x * 256 + threadIdx.x;       // 131072
    int b = idx >> 15, rem = idx & 32767;
    int icp = rem >> 10, px = rem & 1023;
    size_t base = (size_t)b * 64 * 65536 + icp * 2048 + px;
    float h0 = 0.5f, h1v = 0.5f;
    #pragma unroll 8
    for (int t = 0; t < 64; t++) {
        size_t off = base + (size_t)t * 65536;
        uint32_t p0 = AB[off], p1 = AB[off + 1024];
        float2 c0 = __half22float2(*(__half2*)&p0);
        float2 c1 = __half22float2(*(__half2*)&p1);
        h0  = fmaf(c0.x, h0,  c0.y);
        h1v = fmaf(c1.x, h1v, c1.y);
        o1p[(size_t)(b * 64 + t) * 32768 + rem] = pkh2(h0, h1v);
    }
    h1[b * 65536 + icp * 2048 + px]        = h0;
    h1[b * 65536 + icp * 2048 + 1024 + px] = h1v;
}

// Scan layer 2: reads packed (a,b); fp32 out (final), float2 stores.
__global__ void __launch_bounds__(256)
scan2_k(const uint32_t* __restrict__ AB,
        float* __restrict__ out, float* __restrict__ h2)
{
    int idx = blockIdx.x * 256 + threadIdx.x;       // 131072 px-pair lanes
    int b = idx >> 15, j = idx & 32767;
    size_t base = (size_t)b * 64 * 32768 + j;
    const uint2* AB2 = (const uint2*)AB;
    float2* o2 = (float2*)out;
    float h0 = 0.5f, h1v = 0.5f;
    #pragma unroll 8
    for (int t = 0; t < 64; t++) {
        size_t off = base + (size_t)t * 32768;
        uint2 p = AB2[off];
        float2 c0 = __half22float2(*(__half2*)&p.x);
        float2 c1 = __half22float2(*(__half2*)&p.y);
        h0  = fmaf(c0.x, h0,  c0.y);
        h1v = fmaf(c1.x, h1v, c1.y);
        o2[off] = make_float2(h0, h1v);
    }
    ((float2*)h2)[b * 32768 + j] = make_float2(h0, h1v);
}

extern "C" void kernel_launch(void* const* d_in, const int* in_sizes, int n_in,
                              void* d_out, int out_size) {
    const float* x  = (const float*)d_in[0];
    const float* w1 = (const float*)d_in[1];
    const float* b1 = (const float*)d_in[2];
    const float* w2 = (const float*)d_in[3];
    const float* b2 = (const float*)d_in[4];
    float* out = (float*)d_out;

    float *pH;
    uint32_t *pAB, *pO1p, *pU1, *pU2;
    cudaGetSymbolAddress((void**)&pAB,  g_AB);
    cudaGetSymbolAddress((void**)&pO1p, g_O1p);
    cudaGetSymbolAddress((void**)&pH,   g_hdump);
    cudaGetSymbolAddress((void**)&pU1,  g_U1);
    cudaGetSymbolAddress((void**)&pU2,  g_U2);

    const int SMEM1 = (16 * 360 + 16 * 16 * 72) * 4;   //  96768
    const int SMEM2 = (32 * 360 + 16 * 32 * 72) * 4;   // 193536
    cudaFuncSetAttribute(conv_wino<32,false>, cudaFuncAttributeMaxDynamicSharedMemorySize, SMEM1);
    cudaFuncSetAttribute(conv_wino<64,true>,  cudaFuncAttributeMaxDynamicSharedMemorySize, SMEM2);

    bool full = (out_size >= TOT + 8 * PLANE);
    float* h1 = full ? (out + TOT)             : pH;
    float* h2 = full ? (out + TOT + 4 * PLANE) : pH;

    pack_u<32><<<128, 256>>>(w1, pU1);
    pack_u<64><<<256, 256>>>(w2, pU2);
    conv_wino<32,false><<<1024, 512, SMEM1>>>(x, pU1, b1, pAB);
    scan1_k<<<512, 256>>>(pAB, pO1p, h1);
    conv_wino<64,true><<<1024, 512, SMEM2>>>(pO1p, pU2, b2, pAB);
    scan2_k<<<512, 256>>>(pAB, out, h2);
}